// round 1
// baseline (speedup 1.0000x reference)
#include <cuda_runtime.h>

// Problem constants
#define BATCH 4
#define CHN   256
#define SEQ   4096
#define DQK   32
#define DV    128
#define PR    192   // 32 theta + 32 phi + 128 g

// Scratch (device globals; no allocation allowed)
__device__ float g_Wcat[PR * CHN];                 // concat(Wt, Wp, Wg)  [192,256]
__device__ float g_proj[(size_t)BATCH * PR * SEQ]; // rows 0-31 theta, 32-63 phi, 64-191 g
__device__ float g_attn[(size_t)BATCH * DV * SEQ]; // attention output [B,128,SEQ]

// ---------------------------------------------------------------------------
// Kernel 0: concatenate weights into one [192,256] matrix
// ---------------------------------------------------------------------------
__global__ void concat_w_kernel(const float* __restrict__ Wt,
                                const float* __restrict__ Wp,
                                const float* __restrict__ Wg) {
    int r = blockIdx.x;
    int c = threadIdx.x;
    float v;
    if (r < 32)       v = Wt[r * CHN + c];
    else if (r < 64)  v = Wp[(r - 32) * CHN + c];
    else              v = Wg[(r - 64) * CHN + c];
    g_Wcat[r * CHN + c] = v;
}

// ---------------------------------------------------------------------------
// Tiled SGEMM: C[b] = A[M,K] * B[b][K,SEQ]   (B batched, A shared)
// BM=BN=64, BK=16, 256 threads, 4x4 microtile.
// EPI==0: plain store. EPI==1: C = gamma*acc + X[b] (residual epilogue)
// ---------------------------------------------------------------------------
template <int KDIM, int EPI>
__global__ void sgemm_kernel(const float* __restrict__ A,
                             const float* __restrict__ Bg,
                             float* __restrict__ Cg,
                             int M,
                             const float* __restrict__ X,
                             const float* __restrict__ gamma_p) {
    const int b = blockIdx.z;
    const float* Bm = Bg + (size_t)b * KDIM * SEQ;
    float* C = Cg + (size_t)b * M * SEQ;

    const int n0   = blockIdx.x * 64;
    const int row0 = blockIdx.y * 64;

    __shared__ float As[16][64];
    __shared__ float Bs[16][64];

    const int t  = threadIdx.x;
    const int tx = t & 15;
    const int ty = t >> 4;

    float acc[4][4];
#pragma unroll
    for (int i = 0; i < 4; i++)
#pragma unroll
        for (int j = 0; j < 4; j++) acc[i][j] = 0.f;

    for (int k0 = 0; k0 < KDIM; k0 += 16) {
        // Load A tile (64 rows x 16 k), transpose into As[k][row]
        {
            int r  = t >> 2;
            int kq = (t & 3) * 4;
            float4 a = *(const float4*)(A + (size_t)(row0 + r) * KDIM + k0 + kq);
            As[kq + 0][r] = a.x;
            As[kq + 1][r] = a.y;
            As[kq + 2][r] = a.z;
            As[kq + 3][r] = a.w;
        }
        // Load B tile (16 k x 64 n), coalesced
        {
            int kk = t >> 4;
            int cq = (t & 15) * 4;
            *(float4*)&Bs[kk][cq] =
                *(const float4*)(Bm + (size_t)(k0 + kk) * SEQ + n0 + cq);
        }
        __syncthreads();

#pragma unroll
        for (int kk = 0; kk < 16; kk++) {
            float4 a4 = *(const float4*)&As[kk][ty * 4];
            float4 b4 = *(const float4*)&Bs[kk][tx * 4];
            float av[4] = {a4.x, a4.y, a4.z, a4.w};
            float bv[4] = {b4.x, b4.y, b4.z, b4.w};
#pragma unroll
            for (int i = 0; i < 4; i++)
#pragma unroll
                for (int j = 0; j < 4; j++) acc[i][j] += av[i] * bv[j];
        }
        __syncthreads();
    }

    float gm = 0.f;
    if (EPI == 1) gm = gamma_p[0];

#pragma unroll
    for (int i = 0; i < 4; i++) {
        size_t off = (size_t)(row0 + ty * 4 + i) * SEQ + n0 + tx * 4;
        float4 r;
        if (EPI == 1) {
            const float* Xb = X + (size_t)b * M * SEQ;
            float4 xr = *(const float4*)(Xb + off);
            r.x = gm * acc[i][0] + xr.x;
            r.y = gm * acc[i][1] + xr.y;
            r.z = gm * acc[i][2] + xr.z;
            r.w = gm * acc[i][3] + xr.w;
        } else {
            r.x = acc[i][0]; r.y = acc[i][1]; r.z = acc[i][2]; r.w = acc[i][3];
        }
        *(float4*)(C + off) = r;
    }
}

// ---------------------------------------------------------------------------
// Flash-attention kernel.
// Block = (query tile of 64, batch). 256 threads (tx 0-15, ty 0-15).
// Thread owns 4 query rows (i0 = ty*4) and 8 V-channels (c = tx + 16*cc).
// Q,K tiles [32][64]; P [64][64]; V [128][68] (padded stride for bank-free
// float4 reads with interleaved channel ownership).
// ---------------------------------------------------------------------------
#define VSTR 68
#define ATTN_SMEM_FLOATS (2048 /*Q*/ + 2048 /*K*/ + 4096 /*P*/ + DV * VSTR)
#define ATTN_SMEM_BYTES  (ATTN_SMEM_FLOATS * 4)

__global__ void flash_attn_kernel() {
    extern __shared__ float sm[];
    float* Qs = sm;            // [32][64]
    float* Ks = sm + 2048;     // [32][64]
    float* Ps = sm + 4096;     // [64][64]
    float* Vs = sm + 8192;     // [128][VSTR]

    const int b  = blockIdx.y;
    const int q0 = blockIdx.x * 64;
    const int t  = threadIdx.x;
    const int tx = t & 15;
    const int ty = t >> 4;
    const int i0 = ty * 4;

    const float* theta = g_proj + (size_t)b * PR * SEQ;          // rows 0-31
    const float* phi   = theta + (size_t)32 * SEQ;               // rows 32-63
    const float* gv    = theta + (size_t)64 * SEQ;               // rows 64-191

    // Load Q tile: Qs[d][i] = theta[d][q0+i]
#pragma unroll
    for (int s = 0; s < 2; s++) {
        int e4 = t + s * 256;          // 512 float4 total
        int d  = e4 >> 4;
        int i4 = (e4 & 15) * 4;
        *(float4*)&Qs[d * 64 + i4] = *(const float4*)(theta + (size_t)d * SEQ + q0 + i4);
    }

    float mI[4], lI[4], O[4][8];
#pragma unroll
    for (int i = 0; i < 4; i++) {
        mI[i] = -1e30f;
        lI[i] = 0.f;
#pragma unroll
        for (int c = 0; c < 8; c++) O[i][c] = 0.f;
    }

    for (int kt = 0; kt < SEQ / 64; kt++) {
        const int m0 = kt * 64;
        __syncthreads();  // previous iteration done with Ks/Vs/Ps (and Qs load visible)

        // Load K tile
#pragma unroll
        for (int s = 0; s < 2; s++) {
            int e4 = t + s * 256;
            int d  = e4 >> 4;
            int j4 = (e4 & 15) * 4;
            *(float4*)&Ks[d * 64 + j4] = *(const float4*)(phi + (size_t)d * SEQ + m0 + j4);
        }
        // Load V tile (g): Vs[c][j], padded stride
#pragma unroll
        for (int s = 0; s < 8; s++) {
            int e4 = t + s * 256;      // 2048 float4 total
            int c  = e4 >> 4;
            int j4 = (e4 & 15) * 4;
            *(float4*)&Vs[c * VSTR + j4] = *(const float4*)(gv + (size_t)c * SEQ + m0 + j4);
        }
        __syncthreads();

        // S[4][4] = Q^T K for this thread's (i,j) microtile
        float S[4][4];
#pragma unroll
        for (int i = 0; i < 4; i++)
#pragma unroll
            for (int j = 0; j < 4; j++) S[i][j] = 0.f;

#pragma unroll
        for (int d = 0; d < DQK; d++) {
            float4 q4 = *(const float4*)&Qs[d * 64 + i0];
            float4 k4 = *(const float4*)&Ks[d * 64 + tx * 4];
            float qv[4] = {q4.x, q4.y, q4.z, q4.w};
            float kv[4] = {k4.x, k4.y, k4.z, k4.w};
#pragma unroll
            for (int i = 0; i < 4; i++)
#pragma unroll
                for (int j = 0; j < 4; j++) S[i][j] += qv[i] * kv[j];
        }

        // Online softmax per query row (reduce across the 16 tx lanes)
#pragma unroll
        for (int i = 0; i < 4; i++) {
            float rm = fmaxf(fmaxf(S[i][0], S[i][1]), fmaxf(S[i][2], S[i][3]));
#pragma unroll
            for (int m = 8; m > 0; m >>= 1)
                rm = fmaxf(rm, __shfl_xor_sync(0xffffffffu, rm, m));
            float mnew = fmaxf(mI[i], rm);
            float sc   = __expf(mI[i] - mnew);
            float rs   = 0.f;
#pragma unroll
            for (int j = 0; j < 4; j++) {
                float p = __expf(S[i][j] - mnew);
                S[i][j] = p;
                rs += p;
            }
#pragma unroll
            for (int m = 8; m > 0; m >>= 1)
                rs += __shfl_xor_sync(0xffffffffu, rs, m);
            lI[i] = lI[i] * sc + rs;
            mI[i] = mnew;
#pragma unroll
            for (int c = 0; c < 8; c++) O[i][c] *= sc;
            *(float4*)&Ps[(i0 + i) * 64 + tx * 4] =
                make_float4(S[i][0], S[i][1], S[i][2], S[i][3]);
        }
        __syncthreads();

        // O += P * V^T : per thread 4 q-rows x 8 channels, float4 along m
#pragma unroll
        for (int j4 = 0; j4 < 16; j4++) {
            float4 p4[4];
#pragma unroll
            for (int i = 0; i < 4; i++)
                p4[i] = *(const float4*)&Ps[(i0 + i) * 64 + j4 * 4];
#pragma unroll
            for (int cc = 0; cc < 8; cc++) {
                float4 v = *(const float4*)&Vs[(tx + cc * 16) * VSTR + j4 * 4];
#pragma unroll
                for (int i = 0; i < 4; i++) {
                    O[i][cc] += p4[i].x * v.x;
                    O[i][cc] += p4[i].y * v.y;
                    O[i][cc] += p4[i].z * v.z;
                    O[i][cc] += p4[i].w * v.w;
                }
            }
        }
    }

    // Normalize + write out: g_attn[b][c][q0+i0+i]
    float* ab = g_attn + (size_t)b * DV * SEQ;
#pragma unroll
    for (int i = 0; i < 4; i++) {
        float inv = 1.f / lI[i];
        int n = q0 + i0 + i;
#pragma unroll
        for (int cc = 0; cc < 8; cc++) {
            int c = tx + cc * 16;
            ab[(size_t)c * SEQ + n] = O[i][cc] * inv;
        }
    }
}

// ---------------------------------------------------------------------------
// Launch
// ---------------------------------------------------------------------------
extern "C" void kernel_launch(void* const* d_in, const int* in_sizes, int n_in,
                              void* d_out, int out_size) {
    const float* x     = (const float*)d_in[0];  // [4,256,4096]
    const float* Wt    = (const float*)d_in[1];  // [32,256]
    const float* Wp    = (const float*)d_in[2];  // [32,256]
    const float* Wg    = (const float*)d_in[3];  // [128,256]
    const float* Wo    = (const float*)d_in[4];  // [256,128]
    const float* gamma = (const float*)d_in[5];  // scalar
    float* out = (float*)d_out;                  // [4,256,4096]

    (void)in_sizes; (void)n_in; (void)out_size;

    float* wcat_p; cudaGetSymbolAddress((void**)&wcat_p, g_Wcat);
    float* proj_p; cudaGetSymbolAddress((void**)&proj_p, g_proj);
    float* attn_p; cudaGetSymbolAddress((void**)&attn_p, g_attn);

    // 0) concat weights
    concat_w_kernel<<<PR, CHN>>>(Wt, Wp, Wg);

    // 1) projections: [192,256] x [256,4096] per batch
    {
        dim3 grid(SEQ / 64, PR / 64, BATCH);
        sgemm_kernel<CHN, 0><<<grid, 256>>>(wcat_p, x, proj_p, PR, nullptr, nullptr);
    }

    // 2) flash attention
    {
        cudaFuncSetAttribute(flash_attn_kernel,
                             cudaFuncAttributeMaxDynamicSharedMemorySize,
                             ATTN_SMEM_BYTES);
        dim3 grid(SEQ / 64, BATCH);
        flash_attn_kernel<<<grid, 256, ATTN_SMEM_BYTES>>>();
    }

    // 3) output projection + residual: out = gamma * (Wo @ attn) + x
    {
        dim3 grid(SEQ / 64, CHN / 64, BATCH);
        sgemm_kernel<DV, 1><<<grid, 256>>>(Wo, attn_p, out, CHN, x, gamma);
    }
}

// round 3
// speedup vs baseline: 2.3673x; 2.3673x over previous
#include <cuda_runtime.h>
#include <cuda_bf16.h>
#include <cstdint>

// Problem constants
#define BATCH 4
#define CHN   256
#define SEQ   4096
#define DV    128
#define PR    192   // 32 theta + 32 phi + 128 g
#define QT    128   // query rows per flash CTA
#define MT    64    // keys per tile
#define NTILE (SEQ / MT)
#define LOG2E 1.4426950408889634f

// ---------------------------------------------------------------------------
// Device scratch (no allocation allowed)
// ---------------------------------------------------------------------------
__device__ float g_Wcat[PR * CHN];
__device__ __align__(16) __nv_bfloat16 g_th_t[(size_t)BATCH * SEQ * 64]; // theta^T [b][n][32hi|32lo]
__device__ __align__(16) __nv_bfloat16 g_ph_t[(size_t)BATCH * SEQ * 64]; // phi^T (pre-scaled by log2e)
__device__ __align__(16) __nv_bfloat16 g_vhi[(size_t)BATCH * DV * SEQ];  // g hi [b][c][n]
__device__ __align__(16) __nv_bfloat16 g_vlo[(size_t)BATCH * DV * SEQ];  // g lo
__device__ float g_attn[(size_t)BATCH * DV * SEQ];

// ---------------------------------------------------------------------------
// Base-ISA PTX helpers (no sm_103a-only instructions!)
// ---------------------------------------------------------------------------
__device__ __forceinline__ uint32_t smem_u32(const void* p) {
    uint32_t a;
    asm("{ .reg .u64 t; cvta.to.shared.u64 t, %1; cvt.u32.u64 %0, t; }" : "=r"(a) : "l"(p));
    return a;
}
__device__ __forceinline__ void cpa16(uint32_t dst, const void* src) {
    asm volatile("cp.async.cg.shared.global [%0], [%1], 16;" :: "r"(dst), "l"(src));
}
#define CP_COMMIT() asm volatile("cp.async.commit_group;" ::: "memory")
#define CP_WAIT0()  asm volatile("cp.async.wait_group 0;" ::: "memory")

__device__ __forceinline__ void ldsm4(uint32_t* r, uint32_t addr) {
    asm volatile("ldmatrix.sync.aligned.m8n8.x4.shared.b16 {%0,%1,%2,%3}, [%4];"
                 : "=r"(r[0]), "=r"(r[1]), "=r"(r[2]), "=r"(r[3]) : "r"(addr));
}
__device__ __forceinline__ void mma_bf16(float* d, const uint32_t* a, const uint32_t* b) {
    asm volatile(
        "mma.sync.aligned.m16n8k16.row.col.f32.bf16.bf16.f32 "
        "{%0,%1,%2,%3}, {%4,%5,%6,%7}, {%8,%9}, {%0,%1,%2,%3};"
        : "+f"(d[0]), "+f"(d[1]), "+f"(d[2]), "+f"(d[3])
        : "r"(a[0]), "r"(a[1]), "r"(a[2]), "r"(a[3]), "r"(b[0]), "r"(b[1]));
}
__device__ __forceinline__ float ex2f(float x) {
    float y;
    asm("ex2.approx.ftz.f32 %0, %1;" : "=f"(y) : "f"(x));
    return y;
}
__device__ __forceinline__ uint32_t pack2(__nv_bfloat16 a, __nv_bfloat16 b) {
    __nv_bfloat162 t = __halves2bfloat162(a, b);
    return *(uint32_t*)&t;
}

// ---------------------------------------------------------------------------
// Kernel 0: weight concat
// ---------------------------------------------------------------------------
__global__ void concat_w_kernel(const float* __restrict__ Wt,
                                const float* __restrict__ Wp,
                                const float* __restrict__ Wg) {
    int r = blockIdx.x, c = threadIdx.x;
    float v;
    if (r < 32)      v = Wt[r * CHN + c];
    else if (r < 64) v = Wp[(r - 32) * CHN + c];
    else             v = Wg[(r - 64) * CHN + c];
    g_Wcat[r * CHN + c] = v;
}

// ---------------------------------------------------------------------------
// Projection GEMM [192,256]x[256,4096]/batch; epilogue -> bf16 hi/lo planes.
// phi rows are pre-scaled by log2e so softmax exp == single ex2.
// ---------------------------------------------------------------------------
__global__ void proj_gemm_kernel(const float* __restrict__ A,
                                 const float* __restrict__ Xg) {
    const int b = blockIdx.z;
    const float* Bm = Xg + (size_t)b * CHN * SEQ;
    const int n0   = blockIdx.x * 64;
    const int row0 = blockIdx.y * 64;

    __shared__ float As[16][64];
    __shared__ float Bs[16][64];

    const int t  = threadIdx.x;
    const int tx = t & 15;
    const int ty = t >> 4;

    float acc[4][4];
#pragma unroll
    for (int i = 0; i < 4; i++)
#pragma unroll
        for (int j = 0; j < 4; j++) acc[i][j] = 0.f;

    for (int k0 = 0; k0 < CHN; k0 += 16) {
        {
            int r  = t >> 2;
            int kq = (t & 3) * 4;
            float4 a = *(const float4*)(A + (size_t)(row0 + r) * CHN + k0 + kq);
            As[kq + 0][r] = a.x; As[kq + 1][r] = a.y;
            As[kq + 2][r] = a.z; As[kq + 3][r] = a.w;
        }
        {
            int kk = t >> 4;
            int cq = (t & 15) * 4;
            *(float4*)&Bs[kk][cq] = *(const float4*)(Bm + (size_t)(k0 + kk) * SEQ + n0 + cq);
        }
        __syncthreads();
#pragma unroll
        for (int kk = 0; kk < 16; kk++) {
            float4 a4 = *(const float4*)&As[kk][ty * 4];
            float4 b4 = *(const float4*)&Bs[kk][tx * 4];
            float av[4] = {a4.x, a4.y, a4.z, a4.w};
            float bv[4] = {b4.x, b4.y, b4.z, b4.w};
#pragma unroll
            for (int i = 0; i < 4; i++)
#pragma unroll
                for (int j = 0; j < 4; j++) acc[i][j] += av[i] * bv[j];
        }
        __syncthreads();
    }

#pragma unroll
    for (int i = 0; i < 4; i++) {
        int r = row0 + ty * 4 + i;
#pragma unroll
        for (int j = 0; j < 4; j++) {
            int n = n0 + tx * 4 + j;
            float v = acc[i][j];
            if (r >= 32 && r < 64) v *= LOG2E;   // fold log2e into phi
            __nv_bfloat16 h = __float2bfloat16(v);
            __nv_bfloat16 l = __float2bfloat16(v - __bfloat162float(h));
            if (r < 32) {
                __nv_bfloat16* base = g_th_t + ((size_t)b * SEQ + n) * 64;
                base[r] = h; base[32 + r] = l;
            } else if (r < 64) {
                __nv_bfloat16* base = g_ph_t + ((size_t)b * SEQ + n) * 64;
                base[r - 32] = h; base[32 + r - 32] = l;
            } else {
                size_t off = ((size_t)b * DV + (r - 64)) * SEQ + n;
                g_vhi[off] = h; g_vlo[off] = l;
            }
        }
    }
}

// ---------------------------------------------------------------------------
// Flash attention via warp-level mma.sync (bf16 3-term hi/lo split).
// 256 threads = 8 warps; warp w owns query rows q0+16w..+15.
// Smem (bytes): QHI 0..10240, QLO 10240..20480 (stride 80B/row)
//               K buf: 20480 + buf*10240 (hi, +5120 lo; 64 rows x 80B)
//               V buf: 40960 + buf*36864 (hi, +18432 lo; 128 rows x 144B)
// Total 114688.
// ---------------------------------------------------------------------------
#define SM_QHI 0
#define SM_QLO 10240
#define SM_K   20480
#define SM_V   40960
#define FLASH_SMEM 114688

__global__ __launch_bounds__(256, 1) void flash_mma_kernel() {
    extern __shared__ char sm[];
    const uint32_t smb = smem_u32(sm);

    const int b  = blockIdx.y;
    const int q0 = blockIdx.x * QT;
    const int tid  = threadIdx.x;
    const int w    = tid >> 5;
    const int lane = tid & 31;
    const uint32_t lm = lane & 7;
    const uint32_t bk = (lane >> 3) & 1;
    const uint32_t bn = (lane >> 4) & 1;

    // ---- async load Q tile
    {
        const char* src = (const char*)(g_th_t + ((size_t)b * SEQ + q0) * 64);
        for (int e = tid; e < 1024; e += 256) {
            int r = e >> 3, s = e & 7;
            uint32_t dst = smb + (s < 4 ? (SM_QHI + r * 80 + s * 16)
                                        : (SM_QLO + r * 80 + (s - 4) * 16));
            cpa16(dst, src + r * 128 + s * 16);
        }
    }
    // ---- K/V tile loader (async)
    auto load_kv = [&](int buf, int m0) {
        const char* ks = (const char*)(g_ph_t + ((size_t)b * SEQ + m0) * 64);
        uint32_t kb = smb + SM_K + buf * 10240;
        for (int e = tid; e < 512; e += 256) {
            int r = e >> 3, s = e & 7;
            uint32_t dst = kb + (s < 4 ? (r * 80 + s * 16) : (5120 + r * 80 + (s - 4) * 16));
            cpa16(dst, ks + r * 128 + s * 16);
        }
        const char* vh = (const char*)(g_vhi + (size_t)b * DV * SEQ + m0);
        const char* vl = (const char*)(g_vlo + (size_t)b * DV * SEQ + m0);
        uint32_t vb = smb + SM_V + buf * 36864;
        for (int e = tid; e < 1024; e += 256) {
            int r = e >> 3, s = e & 7;
            cpa16(vb + r * 144 + s * 16,         vh + (size_t)r * (SEQ * 2) + s * 16);
            cpa16(vb + 18432 + r * 144 + s * 16, vl + (size_t)r * (SEQ * 2) + s * 16);
        }
    };
    load_kv(0, 0);
    CP_COMMIT();
    CP_WAIT0();
    __syncthreads();

    // ---- Q fragments (held in regs for entire kernel)
    uint32_t qh[2][4], ql[2][4];
#pragma unroll
    for (int ks = 0; ks < 2; ks++) {
        uint32_t a = smb + SM_QHI + (w * 16 + bk * 8 + lm) * 80 + (ks * 16 + bn * 8) * 2;
        ldsm4(qh[ks], a);
        ldsm4(ql[ks], a + (SM_QLO - SM_QHI));
    }

    float oacc[16][4];
#pragma unroll
    for (int j = 0; j < 16; j++)
#pragma unroll
        for (int k = 0; k < 4; k++) oacc[j][k] = 0.f;
    float l0 = 0.f, l1 = 0.f;

    for (int t = 0; t < NTILE; t++) {
        const int buf = t & 1;
        if (t + 1 < NTILE) load_kv(buf ^ 1, (t + 1) * MT);
        CP_COMMIT();

        // ---- S = Q K^T (3-term bf16 split), fragment accumulators
        float sacc[8][4];
#pragma unroll
        for (int j = 0; j < 8; j++)
#pragma unroll
            for (int k = 0; k < 4; k++) sacc[j][k] = 0.f;

        const uint32_t kb = smb + SM_K + buf * 10240;
#pragma unroll
        for (int ks = 0; ks < 2; ks++) {
#pragma unroll
            for (int jj = 0; jj < 4; jj++) {
                uint32_t addr = kb + (jj * 16 + bn * 8 + lm) * 80 + (ks * 16 + bk * 8) * 2;
                uint32_t kh[4], kl[4];
                ldsm4(kh, addr);
                ldsm4(kl, addr + 5120);
                mma_bf16(sacc[2 * jj],     qh[ks], kh);
                mma_bf16(sacc[2 * jj],     qh[ks], kl);
                mma_bf16(sacc[2 * jj],     ql[ks], kh);
                mma_bf16(sacc[2 * jj + 1], qh[ks], kh + 2);
                mma_bf16(sacc[2 * jj + 1], qh[ks], kl + 2);
                mma_bf16(sacc[2 * jj + 1], ql[ks], kh + 2);
            }
        }

        // ---- softmax numerators (phi pre-scaled by log2e -> p = ex2(S'))
        uint32_t ph_[8][2], pl_[8][2];
#pragma unroll
        for (int j = 0; j < 8; j++) {
            float p0 = ex2f(sacc[j][0]);
            float p1 = ex2f(sacc[j][1]);
            float p2 = ex2f(sacc[j][2]);
            float p3 = ex2f(sacc[j][3]);
            l0 += p0 + p1;
            l1 += p2 + p3;
            __nv_bfloat16 h0 = __float2bfloat16(p0), h1 = __float2bfloat16(p1);
            __nv_bfloat16 h2 = __float2bfloat16(p2), h3 = __float2bfloat16(p3);
            ph_[j][0] = pack2(h0, h1);
            ph_[j][1] = pack2(h2, h3);
            pl_[j][0] = pack2(__float2bfloat16(p0 - __bfloat162float(h0)),
                              __float2bfloat16(p1 - __bfloat162float(h1)));
            pl_[j][1] = pack2(__float2bfloat16(p2 - __bfloat162float(h2)),
                              __float2bfloat16(p3 - __bfloat162float(h3)));
        }

        // ---- O += P V^T (3-term)
        const uint32_t vb = smb + SM_V + buf * 36864;
#pragma unroll
        for (int kk = 0; kk < 4; kk++) {
            uint32_t pah[4] = {ph_[2 * kk][0], ph_[2 * kk][1], ph_[2 * kk + 1][0], ph_[2 * kk + 1][1]};
            uint32_t pal[4] = {pl_[2 * kk][0], pl_[2 * kk][1], pl_[2 * kk + 1][0], pl_[2 * kk + 1][1]};
#pragma unroll
            for (int jj = 0; jj < 8; jj++) {
                uint32_t addr = vb + (jj * 16 + bn * 8 + lm) * 144 + (kk * 16 + bk * 8) * 2;
                uint32_t vh4[4], vl4[4];
                ldsm4(vh4, addr);
                ldsm4(vl4, addr + 18432);
                mma_bf16(oacc[2 * jj],     pah, vh4);
                mma_bf16(oacc[2 * jj],     pah, vl4);
                mma_bf16(oacc[2 * jj],     pal, vh4);
                mma_bf16(oacc[2 * jj + 1], pah, vh4 + 2);
                mma_bf16(oacc[2 * jj + 1], pah, vl4 + 2);
                mma_bf16(oacc[2 * jj + 1], pal, vh4 + 2);
            }
        }

        CP_WAIT0();
        __syncthreads();
    }

    // ---- epilogue: row-sum reduce within quads, normalize, store
    l0 += __shfl_xor_sync(0xffffffffu, l0, 1);
    l0 += __shfl_xor_sync(0xffffffffu, l0, 2);
    l1 += __shfl_xor_sync(0xffffffffu, l1, 1);
    l1 += __shfl_xor_sync(0xffffffffu, l1, 2);
    const float inv0 = 1.f / l0;
    const float inv1 = 1.f / l1;

    float* ab = g_attn + (size_t)b * DV * SEQ;
    const int r0 = q0 + w * 16 + (lane >> 2);
    const int qc = (lane & 3) * 2;
#pragma unroll
    for (int j = 0; j < 16; j++) {
        int c = j * 8 + qc;
        ab[(size_t)c * SEQ + r0]           = oacc[j][0] * inv0;
        ab[(size_t)(c + 1) * SEQ + r0]     = oacc[j][1] * inv0;
        ab[(size_t)c * SEQ + r0 + 8]       = oacc[j][2] * inv1;
        ab[(size_t)(c + 1) * SEQ + r0 + 8] = oacc[j][3] * inv1;
    }
}

// ---------------------------------------------------------------------------
// Output GEMM: out = gamma * (Wo @ attn) + x
// ---------------------------------------------------------------------------
__global__ void out_gemm_kernel(const float* __restrict__ A,
                                const float* __restrict__ Xg,
                                float* __restrict__ Cg,
                                const float* __restrict__ gamma_p) {
    const int b = blockIdx.z;
    const float* Bm = g_attn + (size_t)b * DV * SEQ;
    float* C = Cg + (size_t)b * CHN * SEQ;
    const int n0   = blockIdx.x * 64;
    const int row0 = blockIdx.y * 64;

    __shared__ float As[16][64];
    __shared__ float Bs[16][64];

    const int t  = threadIdx.x;
    const int tx = t & 15;
    const int ty = t >> 4;

    float acc[4][4];
#pragma unroll
    for (int i = 0; i < 4; i++)
#pragma unroll
        for (int j = 0; j < 4; j++) acc[i][j] = 0.f;

    for (int k0 = 0; k0 < DV; k0 += 16) {
        {
            int r  = t >> 2;
            int kq = (t & 3) * 4;
            float4 a = *(const float4*)(A + (size_t)(row0 + r) * DV + k0 + kq);
            As[kq + 0][r] = a.x; As[kq + 1][r] = a.y;
            As[kq + 2][r] = a.z; As[kq + 3][r] = a.w;
        }
        {
            int kk = t >> 4;
            int cq = (t & 15) * 4;
            *(float4*)&Bs[kk][cq] = *(const float4*)(Bm + (size_t)(k0 + kk) * SEQ + n0 + cq);
        }
        __syncthreads();
#pragma unroll
        for (int kk = 0; kk < 16; kk++) {
            float4 a4 = *(const float4*)&As[kk][ty * 4];
            float4 b4 = *(const float4*)&Bs[kk][tx * 4];
            float av[4] = {a4.x, a4.y, a4.z, a4.w};
            float bv[4] = {b4.x, b4.y, b4.z, b4.w};
#pragma unroll
            for (int i = 0; i < 4; i++)
#pragma unroll
                for (int j = 0; j < 4; j++) acc[i][j] += av[i] * bv[j];
        }
        __syncthreads();
    }

    const float gm = gamma_p[0];
    const float* Xb = Xg + (size_t)b * CHN * SEQ;
#pragma unroll
    for (int i = 0; i < 4; i++) {
        size_t off = (size_t)(row0 + ty * 4 + i) * SEQ + n0 + tx * 4;
        float4 xr = *(const float4*)(Xb + off);
        float4 r;
        r.x = gm * acc[i][0] + xr.x;
        r.y = gm * acc[i][1] + xr.y;
        r.z = gm * acc[i][2] + xr.z;
        r.w = gm * acc[i][3] + xr.w;
        *(float4*)(C + off) = r;
    }
}

// ---------------------------------------------------------------------------
// Launch
// ---------------------------------------------------------------------------
extern "C" void kernel_launch(void* const* d_in, const int* in_sizes, int n_in,
                              void* d_out, int out_size) {
    const float* x     = (const float*)d_in[0];
    const float* Wt    = (const float*)d_in[1];
    const float* Wp    = (const float*)d_in[2];
    const float* Wg    = (const float*)d_in[3];
    const float* Wo    = (const float*)d_in[4];
    const float* gamma = (const float*)d_in[5];
    float* out = (float*)d_out;
    (void)in_sizes; (void)n_in; (void)out_size;

    float* wcat_p; cudaGetSymbolAddress((void**)&wcat_p, g_Wcat);

    concat_w_kernel<<<PR, CHN>>>(Wt, Wp, Wg);

    {
        dim3 grid(SEQ / 64, PR / 64, BATCH);
        proj_gemm_kernel<<<grid, 256>>>(wcat_p, x);
    }
    {
        cudaFuncSetAttribute(flash_mma_kernel,
                             cudaFuncAttributeMaxDynamicSharedMemorySize, FLASH_SMEM);
        dim3 grid(SEQ / QT, BATCH);
        flash_mma_kernel<<<grid, 256, FLASH_SMEM>>>();
    }
    {
        dim3 grid(SEQ / 64, CHN / 64, BATCH);
        out_gemm_kernel<<<grid, 256>>>(Wo, x, out, gamma);
    }
}

// round 4
// speedup vs baseline: 2.9919x; 1.2638x over previous
#include <cuda_runtime.h>
#include <cuda_bf16.h>
#include <cstdint>

#define BATCH 4
#define CHN   256
#define SEQ   4096
#define DV    128
#define QT    128
#define MT    64
#define NTILE (SEQ / MT)
#define LOG2E 1.4426950408889634f

// ---------------------------------------------------------------------------
// Device scratch (no allocation allowed)
// ---------------------------------------------------------------------------
__device__ __align__(16) __nv_bfloat16 g_wch[192 * 256];  // concat(Wt,Wp,Wg) hi
__device__ __align__(16) __nv_bfloat16 g_wcl[192 * 256];  // lo
__device__ __align__(16) __nv_bfloat16 g_woh[256 * 128];  // Wo hi
__device__ __align__(16) __nv_bfloat16 g_wol[256 * 128];  // Wo lo
__device__ __align__(16) __nv_bfloat16 g_xth[(size_t)BATCH * SEQ * CHN]; // x^T hi [b][n][c]
__device__ __align__(16) __nv_bfloat16 g_xtl[(size_t)BATCH * SEQ * CHN]; // x^T lo
__device__ __align__(16) __nv_bfloat16 g_th_t[(size_t)BATCH * SEQ * 64]; // theta^T [n][32hi|32lo]
__device__ __align__(16) __nv_bfloat16 g_ph_t[(size_t)BATCH * SEQ * 64]; // phi^T (x log2e)
__device__ __align__(16) __nv_bfloat16 g_vth[(size_t)BATCH * SEQ * DV];  // g^T hi [b][n][c]
__device__ __align__(16) __nv_bfloat16 g_vtl[(size_t)BATCH * SEQ * DV];  // g^T lo
__device__ __align__(16) __nv_bfloat16 g_ath[(size_t)BATCH * SEQ * DV];  // attn^T hi [b][n][c]
__device__ __align__(16) __nv_bfloat16 g_atl[(size_t)BATCH * SEQ * DV];  // attn^T lo

// ---------------------------------------------------------------------------
// Base-ISA PTX helpers
// ---------------------------------------------------------------------------
__device__ __forceinline__ uint32_t smem_u32(const void* p) {
    uint32_t a;
    asm("{ .reg .u64 t; cvta.to.shared.u64 t, %1; cvt.u32.u64 %0, t; }" : "=r"(a) : "l"(p));
    return a;
}
__device__ __forceinline__ void cpa16(uint32_t dst, const void* src) {
    asm volatile("cp.async.cg.shared.global [%0], [%1], 16;" :: "r"(dst), "l"(src));
}
#define CP_COMMIT() asm volatile("cp.async.commit_group;" ::: "memory")
#define CP_WAIT0()  asm volatile("cp.async.wait_group 0;" ::: "memory")
#define CP_WAIT1()  asm volatile("cp.async.wait_group 1;" ::: "memory")

__device__ __forceinline__ void ldsm4(uint32_t* r, uint32_t addr) {
    asm volatile("ldmatrix.sync.aligned.m8n8.x4.shared.b16 {%0,%1,%2,%3}, [%4];"
                 : "=r"(r[0]), "=r"(r[1]), "=r"(r[2]), "=r"(r[3]) : "r"(addr));
}
__device__ __forceinline__ void ldsm4_t(uint32_t* r, uint32_t addr) {
    asm volatile("ldmatrix.sync.aligned.m8n8.x4.trans.shared.b16 {%0,%1,%2,%3}, [%4];"
                 : "=r"(r[0]), "=r"(r[1]), "=r"(r[2]), "=r"(r[3]) : "r"(addr));
}
__device__ __forceinline__ void mma_bf16(float* d, const uint32_t* a, uint32_t b0, uint32_t b1) {
    asm volatile(
        "mma.sync.aligned.m16n8k16.row.col.f32.bf16.bf16.f32 "
        "{%0,%1,%2,%3}, {%4,%5,%6,%7}, {%8,%9}, {%0,%1,%2,%3};"
        : "+f"(d[0]), "+f"(d[1]), "+f"(d[2]), "+f"(d[3])
        : "r"(a[0]), "r"(a[1]), "r"(a[2]), "r"(a[3]), "r"(b0), "r"(b1));
}
__device__ __forceinline__ float ex2f(float x) {
    float y;
    asm("ex2.approx.ftz.f32 %0, %1;" : "=f"(y) : "f"(x));
    return y;
}
// pack two floats -> bf16x2 {lo=a, hi=b}
__device__ __forceinline__ uint32_t cvt2(float a, float b) {
    uint32_t r;
    asm("cvt.rn.bf16x2.f32 %0, %1, %2;" : "=r"(r) : "f"(b), "f"(a));
    return r;
}
// hi/lo split of a pair -> packed bf16x2 words
__device__ __forceinline__ void split2(float a, float b, uint32_t& hw, uint32_t& lw) {
    hw = cvt2(a, b);
    float ha = __uint_as_float(hw << 16);
    float hb = __uint_as_float(hw & 0xffff0000u);
    lw = cvt2(a - ha, b - hb);
}

// ---------------------------------------------------------------------------
// Prep kernels
// ---------------------------------------------------------------------------
__global__ void prep_w_kernel(const float* __restrict__ Wt, const float* __restrict__ Wp,
                              const float* __restrict__ Wg, const float* __restrict__ Wo) {
    int r = blockIdx.x, c = threadIdx.x;
    if (r < 192) {
        float v = (r < 32) ? Wt[r * CHN + c]
                 : (r < 64) ? Wp[(r - 32) * CHN + c]
                            : Wg[(r - 64) * CHN + c];
        __nv_bfloat16 h = __float2bfloat16(v);
        g_wch[r * CHN + c] = h;
        g_wcl[r * CHN + c] = __float2bfloat16(v - __bfloat162float(h));
    } else if (c < 128) {
        int rr = r - 192;
        float v = Wo[rr * DV + c];
        __nv_bfloat16 h = __float2bfloat16(v);
        g_woh[rr * DV + c] = h;
        g_wol[rr * DV + c] = __float2bfloat16(v - __bfloat162float(h));
    }
}

// x [b][256][4096] -> x^T hi/lo [b][4096][256]
__global__ void transpose_x_kernel(const float* __restrict__ Xg) {
    __shared__ float tile[32][33];
    int b  = blockIdx.z;
    int n0 = blockIdx.x * 32;
    int c0 = blockIdx.y * 32;
    int tx = threadIdx.x & 31, ty = threadIdx.x >> 5;
    const float* xb = Xg + (size_t)b * CHN * SEQ;
#pragma unroll
    for (int i = 0; i < 32; i += 8)
        tile[ty + i][tx] = xb[(size_t)(c0 + ty + i) * SEQ + n0 + tx];
    __syncthreads();
#pragma unroll
    for (int i = 0; i < 32; i += 8) {
        float v = tile[tx][ty + i];          // x[c0+tx][n0+ty+i]
        __nv_bfloat16 h = __float2bfloat16(v);
        size_t off = ((size_t)b * SEQ + n0 + ty + i) * CHN + c0 + tx;
        g_xth[off] = h;
        g_xtl[off] = __float2bfloat16(v - __bfloat162float(h));
    }
}

// ---------------------------------------------------------------------------
// Projection GEMM via mma.sync: C[n][out192] = x^T[n][c] * Wcat[out][c]
// CTA: 128 n-rows x 64 out-cols; 8 warps x 16 rows. K = 256 in 4 chunks of 64.
// smem per buf: Ah[128][144] Al Bh[64][144] Bl = 55296; x2 bufs = 110592.
// ---------------------------------------------------------------------------
#define PJ_SMEM 110592
__global__ __launch_bounds__(256, 1) void proj_mma_kernel() {
    extern __shared__ char sm[];
    const uint32_t smb = smem_u32(sm);
    const int b    = blockIdx.z;
    const int out0 = blockIdx.y * 64;
    const int n0   = blockIdx.x * 128;
    const int tid  = threadIdx.x;
    const int w    = tid >> 5;
    const int lane = tid & 31;
    const uint32_t lm = lane & 7;
    const uint32_t bk = (lane >> 3) & 1;
    const uint32_t bn = (lane >> 4) & 1;

    auto load_chunk = [&](int buf, int k0) {
        uint32_t base = smb + buf * 55296;
        const char* xh = (const char*)(g_xth + ((size_t)b * SEQ + n0) * CHN + k0);
        const char* xl = (const char*)(g_xtl + ((size_t)b * SEQ + n0) * CHN + k0);
        for (int e = tid; e < 1024; e += 256) {
            int r = e >> 3, s = e & 7;
            cpa16(base + r * 144 + s * 16,         xh + (size_t)r * 512 + s * 16);
            cpa16(base + 18432 + r * 144 + s * 16, xl + (size_t)r * 512 + s * 16);
        }
        const char* wh = (const char*)(g_wch + (size_t)out0 * CHN + k0);
        const char* wl = (const char*)(g_wcl + (size_t)out0 * CHN + k0);
        for (int e = tid; e < 512; e += 256) {
            int r = e >> 3, s = e & 7;
            cpa16(base + 36864 + r * 144 + s * 16, wh + (size_t)r * 512 + s * 16);
            cpa16(base + 46080 + r * 144 + s * 16, wl + (size_t)r * 512 + s * 16);
        }
    };

    float oacc[8][4];
#pragma unroll
    for (int g = 0; g < 8; g++)
#pragma unroll
        for (int k = 0; k < 4; k++) oacc[g][k] = 0.f;

    load_chunk(0, 0);
    CP_COMMIT();

    for (int kb = 0; kb < 4; kb++) {
        int buf = kb & 1;
        if (kb < 3) { load_chunk(buf ^ 1, (kb + 1) * 64); CP_COMMIT(); CP_WAIT1(); }
        else        { CP_WAIT0(); }
        __syncthreads();

        uint32_t ab = smb + buf * 55296;
        uint32_t bb = ab + 36864;
#pragma unroll
        for (int kc = 0; kc < 4; kc++) {
            uint32_t ah4[4], al4[4];
            uint32_t aaddr = ab + (w * 16 + bk * 8 + lm) * 144 + (kc * 16 + bn * 8) * 2;
            ldsm4(ah4, aaddr);
            ldsm4(al4, aaddr + 18432);
#pragma unroll
            for (int jj = 0; jj < 4; jj++) {
                uint32_t baddr = bb + (jj * 16 + bn * 8 + lm) * 144 + (kc * 16 + bk * 8) * 2;
                uint32_t bh4[4], bl4[4];
                ldsm4(bh4, baddr);
                ldsm4(bl4, baddr + 9216);
                mma_bf16(oacc[2 * jj],     ah4, bh4[0], bh4[1]);
                mma_bf16(oacc[2 * jj],     ah4, bl4[0], bl4[1]);
                mma_bf16(oacc[2 * jj],     al4, bh4[0], bh4[1]);
                mma_bf16(oacc[2 * jj + 1], ah4, bh4[2], bh4[3]);
                mma_bf16(oacc[2 * jj + 1], ah4, bl4[2], bl4[3]);
                mma_bf16(oacc[2 * jj + 1], al4, bh4[2], bh4[3]);
            }
        }
        __syncthreads();
    }

    // epilogue: write theta^T / phi^T (x log2e) / v^T hi+lo
    const int rbase = n0 + w * 16 + (lane >> 2);
    const int qc = (lane & 3) * 2;
#pragma unroll
    for (int g = 0; g < 8; g++) {
        int out = out0 + g * 8 + qc;
#pragma unroll
        for (int rr = 0; rr < 2; rr++) {
            int n = rbase + rr * 8;
            float v0 = oacc[g][rr * 2], v1 = oacc[g][rr * 2 + 1];
            uint32_t hw, lw;
            if (out < 32) {
                split2(v0, v1, hw, lw);
                __nv_bfloat16* base = g_th_t + ((size_t)b * SEQ + n) * 64;
                *(uint32_t*)(base + out) = hw;
                *(uint32_t*)(base + 32 + out) = lw;
            } else if (out < 64) {
                split2(v0 * LOG2E, v1 * LOG2E, hw, lw);
                __nv_bfloat16* base = g_ph_t + ((size_t)b * SEQ + n) * 64;
                *(uint32_t*)(base + (out - 32)) = hw;
                *(uint32_t*)(base + out) = lw;
            } else {
                split2(v0, v1, hw, lw);
                size_t off = ((size_t)b * SEQ + n) * DV + (out - 64);
                *(uint32_t*)(g_vth + off) = hw;
                *(uint32_t*)(g_vtl + off) = lw;
            }
        }
    }
}

// ---------------------------------------------------------------------------
// Flash attention (mma.sync, bf16 3-term, no-max softmax).
// Smem: QHI 0..10240 QLO 10240..20480 (80B rows)
//       K buf: 20480 + buf*10240 (hi, +5120 lo)
//       V buf: 40960 + buf*34816  ([64 m][272B] hi, +17408 lo)   total 110592
// ---------------------------------------------------------------------------
#define SM_QHI 0
#define SM_QLO 10240
#define SM_K   20480
#define SM_V   40960
#define FLASH_SMEM 110592

__global__ __launch_bounds__(256, 1) void flash_mma_kernel() {
    extern __shared__ char sm[];
    const uint32_t smb = smem_u32(sm);

    const int b  = blockIdx.y;
    const int q0 = blockIdx.x * QT;
    const int tid  = threadIdx.x;
    const int w    = tid >> 5;
    const int lane = tid & 31;
    const uint32_t lm = lane & 7;
    const uint32_t bk = (lane >> 3) & 1;
    const uint32_t bn = (lane >> 4) & 1;

    // Q tile
    {
        const char* src = (const char*)(g_th_t + ((size_t)b * SEQ + q0) * 64);
        for (int e = tid; e < 1024; e += 256) {
            int r = e >> 3, s = e & 7;
            uint32_t dst = smb + (s < 4 ? (SM_QHI + r * 80 + s * 16)
                                        : (SM_QLO + r * 80 + (s - 4) * 16));
            cpa16(dst, src + r * 128 + s * 16);
        }
    }
    auto load_kv = [&](int buf, int m0) {
        const char* ks = (const char*)(g_ph_t + ((size_t)b * SEQ + m0) * 64);
        uint32_t kb = smb + SM_K + buf * 10240;
        for (int e = tid; e < 512; e += 256) {
            int r = e >> 3, s = e & 7;
            uint32_t dst = kb + (s < 4 ? (r * 80 + s * 16) : (5120 + r * 80 + (s - 4) * 16));
            cpa16(dst, ks + r * 128 + s * 16);
        }
        const char* vh = (const char*)(g_vth + ((size_t)b * SEQ + m0) * DV);
        const char* vl = (const char*)(g_vtl + ((size_t)b * SEQ + m0) * DV);
        uint32_t vb = smb + SM_V + buf * 34816;
        for (int e = tid; e < 1024; e += 256) {
            int r = e >> 4, s = e & 15;
            cpa16(vb + r * 272 + s * 16,         vh + (size_t)r * 256 + s * 16);
            cpa16(vb + 17408 + r * 272 + s * 16, vl + (size_t)r * 256 + s * 16);
        }
    };
    load_kv(0, 0);
    CP_COMMIT();
    CP_WAIT0();
    __syncthreads();

    uint32_t qh[2][4], ql[2][4];
#pragma unroll
    for (int ks = 0; ks < 2; ks++) {
        uint32_t a = smb + SM_QHI + (w * 16 + bk * 8 + lm) * 80 + (ks * 16 + bn * 8) * 2;
        ldsm4(qh[ks], a);
        ldsm4(ql[ks], a + (SM_QLO - SM_QHI));
    }

    float oacc[16][4];
#pragma unroll
    for (int j = 0; j < 16; j++)
#pragma unroll
        for (int k = 0; k < 4; k++) oacc[j][k] = 0.f;
    float l0 = 0.f, l1 = 0.f;

    for (int t = 0; t < NTILE; t++) {
        const int buf = t & 1;
        if (t + 1 < NTILE) load_kv(buf ^ 1, (t + 1) * MT);
        CP_COMMIT();

        // S = Q K^T
        float sacc[8][4];
#pragma unroll
        for (int j = 0; j < 8; j++)
#pragma unroll
            for (int k = 0; k < 4; k++) sacc[j][k] = 0.f;

        const uint32_t kb = smb + SM_K + buf * 10240;
#pragma unroll
        for (int ks = 0; ks < 2; ks++) {
#pragma unroll
            for (int jj = 0; jj < 4; jj++) {
                uint32_t addr = kb + (jj * 16 + bn * 8 + lm) * 80 + (ks * 16 + bk * 8) * 2;
                uint32_t kh[4], kl[4];
                ldsm4(kh, addr);
                ldsm4(kl, addr + 5120);
                mma_bf16(sacc[2 * jj],     qh[ks], kh[0], kh[1]);
                mma_bf16(sacc[2 * jj],     qh[ks], kl[0], kl[1]);
                mma_bf16(sacc[2 * jj],     ql[ks], kh[0], kh[1]);
                mma_bf16(sacc[2 * jj + 1], qh[ks], kh[2], kh[3]);
                mma_bf16(sacc[2 * jj + 1], qh[ks], kl[2], kl[3]);
                mma_bf16(sacc[2 * jj + 1], ql[ks], kh[2], kh[3]);
            }
        }

        // softmax numerators (phi prescaled by log2e)
        uint32_t ph_[8][2], pl_[8][2];
#pragma unroll
        for (int j = 0; j < 8; j++) {
            float p0 = ex2f(sacc[j][0]);
            float p1 = ex2f(sacc[j][1]);
            float p2 = ex2f(sacc[j][2]);
            float p3 = ex2f(sacc[j][3]);
            l0 += p0 + p1;
            l1 += p2 + p3;
            split2(p0, p1, ph_[j][0], pl_[j][0]);
            split2(p2, p3, ph_[j][1], pl_[j][1]);
        }

        // O += P V^T  (V from [m][ch] storage via ldmatrix.trans)
        const uint32_t vb = smb + SM_V + buf * 34816;
#pragma unroll
        for (int kk = 0; kk < 4; kk++) {
            uint32_t pah[4] = {ph_[2 * kk][0], ph_[2 * kk][1], ph_[2 * kk + 1][0], ph_[2 * kk + 1][1]};
            uint32_t pal[4] = {pl_[2 * kk][0], pl_[2 * kk][1], pl_[2 * kk + 1][0], pl_[2 * kk + 1][1]};
#pragma unroll
            for (int jj = 0; jj < 8; jj++) {
                uint32_t addr = vb + (kk * 16 + bk * 8 + lm) * 272 + (jj * 16 + bn * 8) * 2;
                uint32_t vh4[4], vl4[4];
                ldsm4_t(vh4, addr);
                ldsm4_t(vl4, addr + 17408);
                mma_bf16(oacc[2 * jj],     pah, vh4[0], vh4[1]);
                mma_bf16(oacc[2 * jj],     pah, vl4[0], vl4[1]);
                mma_bf16(oacc[2 * jj],     pal, vh4[0], vh4[1]);
                mma_bf16(oacc[2 * jj + 1], pah, vh4[2], vh4[3]);
                mma_bf16(oacc[2 * jj + 1], pah, vl4[2], vl4[3]);
                mma_bf16(oacc[2 * jj + 1], pal, vh4[2], vh4[3]);
            }
        }

        CP_WAIT0();
        __syncthreads();
    }

    // epilogue: reduce row sums, normalize, write attn^T hi/lo bf16
    l0 += __shfl_xor_sync(0xffffffffu, l0, 1);
    l0 += __shfl_xor_sync(0xffffffffu, l0, 2);
    l1 += __shfl_xor_sync(0xffffffffu, l1, 1);
    l1 += __shfl_xor_sync(0xffffffffu, l1, 2);
    const float inv0 = 1.f / l0;
    const float inv1 = 1.f / l1;

    const int r0 = q0 + w * 16 + (lane >> 2);
    const int qc = (lane & 3) * 2;
#pragma unroll
    for (int j = 0; j < 16; j++) {
        int c = j * 8 + qc;
        uint32_t hw, lw;
        split2(oacc[j][0] * inv0, oacc[j][1] * inv0, hw, lw);
        size_t off = ((size_t)b * SEQ + r0) * DV + c;
        *(uint32_t*)(g_ath + off) = hw;
        *(uint32_t*)(g_atl + off) = lw;
        split2(oacc[j][2] * inv1, oacc[j][3] * inv1, hw, lw);
        size_t off2 = ((size_t)b * SEQ + r0 + 8) * DV + c;
        *(uint32_t*)(g_ath + off2) = hw;
        *(uint32_t*)(g_atl + off2) = lw;
    }
}

// ---------------------------------------------------------------------------
// Output GEMM via mma.sync: out[c_out][n] = gamma*(Wo[c_out][c] . attn^T[n][c]) + x
// CTA: 128 c_out rows x 64 n cols. K = 128 fully resident.
// smem: Ah[128][272]=34816 @0, Al @34816, Bh[64][272] @69632, Bl @87040.
// ---------------------------------------------------------------------------
#define OM_SMEM 104448
__global__ __launch_bounds__(256) void out_mma_kernel(const float* __restrict__ Xg,
                                                      float* __restrict__ Cg,
                                                      const float* __restrict__ gamma_p) {
    extern __shared__ char sm[];
    const uint32_t smb = smem_u32(sm);
    const int b  = blockIdx.z;
    const int n0 = blockIdx.x * 64;
    const int m0 = blockIdx.y * 128;
    const int tid  = threadIdx.x;
    const int w    = tid >> 5;
    const int lane = tid & 31;
    const uint32_t lm = lane & 7;
    const uint32_t bk = (lane >> 3) & 1;
    const uint32_t bn = (lane >> 4) & 1;

    {
        const char* ah = (const char*)(g_woh + (size_t)m0 * DV);
        const char* al = (const char*)(g_wol + (size_t)m0 * DV);
        for (int e = tid; e < 2048; e += 256) {
            int r = e >> 4, s = e & 15;
            cpa16(smb + r * 272 + s * 16,         ah + (size_t)r * 256 + s * 16);
            cpa16(smb + 34816 + r * 272 + s * 16, al + (size_t)r * 256 + s * 16);
        }
        const char* bh = (const char*)(g_ath + ((size_t)b * SEQ + n0) * DV);
        const char* bl = (const char*)(g_atl + ((size_t)b * SEQ + n0) * DV);
        for (int e = tid; e < 1024; e += 256) {
            int r = e >> 4, s = e & 15;
            cpa16(smb + 69632 + r * 272 + s * 16, bh + (size_t)r * 256 + s * 16);
            cpa16(smb + 87040 + r * 272 + s * 16, bl + (size_t)r * 256 + s * 16);
        }
    }
    CP_COMMIT();
    CP_WAIT0();
    __syncthreads();

    float oacc[8][4];
#pragma unroll
    for (int g = 0; g < 8; g++)
#pragma unroll
        for (int k = 0; k < 4; k++) oacc[g][k] = 0.f;

#pragma unroll
    for (int kc = 0; kc < 8; kc++) {
        uint32_t ah4[4], al4[4];
        uint32_t aaddr = smb + (w * 16 + bk * 8 + lm) * 272 + (kc * 16 + bn * 8) * 2;
        ldsm4(ah4, aaddr);
        ldsm4(al4, aaddr + 34816);
#pragma unroll
        for (int jj = 0; jj < 4; jj++) {
            uint32_t baddr = smb + 69632 + (jj * 16 + bn * 8 + lm) * 272 + (kc * 16 + bk * 8) * 2;
            uint32_t bh4[4], bl4[4];
            ldsm4(bh4, baddr);
            ldsm4(bl4, baddr + 17408);
            mma_bf16(oacc[2 * jj],     ah4, bh4[0], bh4[1]);
            mma_bf16(oacc[2 * jj],     ah4, bl4[0], bl4[1]);
            mma_bf16(oacc[2 * jj],     al4, bh4[0], bh4[1]);
            mma_bf16(oacc[2 * jj + 1], ah4, bh4[2], bh4[3]);
            mma_bf16(oacc[2 * jj + 1], ah4, bl4[2], bl4[3]);
            mma_bf16(oacc[2 * jj + 1], al4, bh4[2], bh4[3]);
        }
    }

    const float gm = gamma_p[0];
    const float* xb = Xg + (size_t)b * CHN * SEQ;
    float* cb = Cg + (size_t)b * CHN * SEQ;
    const int r = m0 + w * 16 + (lane >> 2);
    const int qc = (lane & 3) * 2;
#pragma unroll
    for (int g = 0; g < 8; g++) {
        int n = n0 + g * 8 + qc;
#pragma unroll
        for (int rr = 0; rr < 2; rr++) {
            int row = r + rr * 8;
            float2 x2 = *(const float2*)(xb + (size_t)row * SEQ + n);
            float2 o;
            o.x = gm * oacc[g][rr * 2]     + x2.x;
            o.y = gm * oacc[g][rr * 2 + 1] + x2.y;
            *(float2*)(cb + (size_t)row * SEQ + n) = o;
        }
    }
}

// ---------------------------------------------------------------------------
// Launch
// ---------------------------------------------------------------------------
extern "C" void kernel_launch(void* const* d_in, const int* in_sizes, int n_in,
                              void* d_out, int out_size) {
    const float* x     = (const float*)d_in[0];
    const float* Wt    = (const float*)d_in[1];
    const float* Wp    = (const float*)d_in[2];
    const float* Wg    = (const float*)d_in[3];
    const float* Wo    = (const float*)d_in[4];
    const float* gamma = (const float*)d_in[5];
    float* out = (float*)d_out;
    (void)in_sizes; (void)n_in; (void)out_size;

    prep_w_kernel<<<448, 256>>>(Wt, Wp, Wg, Wo);
    transpose_x_kernel<<<dim3(SEQ / 32, CHN / 32, BATCH), 256>>>(x);

    cudaFuncSetAttribute(proj_mma_kernel, cudaFuncAttributeMaxDynamicSharedMemorySize, PJ_SMEM);
    proj_mma_kernel<<<dim3(SEQ / 128, 3, BATCH), 256, PJ_SMEM>>>();

    cudaFuncSetAttribute(flash_mma_kernel, cudaFuncAttributeMaxDynamicSharedMemorySize, FLASH_SMEM);
    flash_mma_kernel<<<dim3(SEQ / QT, BATCH), 256, FLASH_SMEM>>>();

    cudaFuncSetAttribute(out_mma_kernel, cudaFuncAttributeMaxDynamicSharedMemorySize, OM_SMEM);
    out_mma_kernel<<<dim3(SEQ / 64, CHN / 128, BATCH), 256, OM_SMEM>>>(x, out, gamma);
}

// round 5
// speedup vs baseline: 3.7601x; 1.2567x over previous
#include <cuda_runtime.h>
#include <cuda_bf16.h>
#include <cstdint>

#define BATCH 4
#define CHN   256
#define SEQ   4096
#define DV    128
#define QT    128
#define MT    64
#define NTILE (SEQ / MT)
#define LOG2E 1.4426950408889634f

// ---------------------------------------------------------------------------
// Device scratch (no allocation allowed)
// ---------------------------------------------------------------------------
__device__ __align__(16) __nv_bfloat16 g_wch[192 * 256];  // concat(Wt,Wp,Wg) hi
__device__ __align__(16) __nv_bfloat16 g_wcl[192 * 256];  // lo
__device__ __align__(16) __nv_bfloat16 g_woh[256 * 128];  // Wo hi
__device__ __align__(16) __nv_bfloat16 g_wol[256 * 128];  // Wo lo
__device__ __align__(16) __nv_bfloat16 g_xth[(size_t)BATCH * SEQ * CHN]; // x^T hi [b][n][c]
__device__ __align__(16) __nv_bfloat16 g_xtl[(size_t)BATCH * SEQ * CHN]; // x^T lo
__device__ __align__(16) __nv_bfloat16 g_th_t[(size_t)BATCH * SEQ * 64]; // theta^T [n][32hi|32lo]
__device__ __align__(16) __nv_bfloat16 g_ph_t[(size_t)BATCH * SEQ * 64]; // phi^T (x log2e)
__device__ __align__(16) __nv_bfloat16 g_vth[(size_t)BATCH * SEQ * DV];  // g^T hi [b][n][c]  (no lo plane)
__device__ __align__(16) __nv_bfloat16 g_ath[(size_t)BATCH * SEQ * DV];  // attn^T hi [b][n][c]
__device__ __align__(16) __nv_bfloat16 g_atl[(size_t)BATCH * SEQ * DV];  // attn^T lo

// ---------------------------------------------------------------------------
// Base-ISA PTX helpers
// ---------------------------------------------------------------------------
__device__ __forceinline__ uint32_t smem_u32(const void* p) {
    uint32_t a;
    asm("{ .reg .u64 t; cvta.to.shared.u64 t, %1; cvt.u32.u64 %0, t; }" : "=r"(a) : "l"(p));
    return a;
}
__device__ __forceinline__ void cpa16(uint32_t dst, const void* src) {
    asm volatile("cp.async.cg.shared.global [%0], [%1], 16;" :: "r"(dst), "l"(src));
}
#define CP_COMMIT() asm volatile("cp.async.commit_group;" ::: "memory")
#define CP_WAIT0()  asm volatile("cp.async.wait_group 0;" ::: "memory")
#define CP_WAIT1()  asm volatile("cp.async.wait_group 1;" ::: "memory")

__device__ __forceinline__ void ldsm4(uint32_t* r, uint32_t addr) {
    asm volatile("ldmatrix.sync.aligned.m8n8.x4.shared.b16 {%0,%1,%2,%3}, [%4];"
                 : "=r"(r[0]), "=r"(r[1]), "=r"(r[2]), "=r"(r[3]) : "r"(addr));
}
__device__ __forceinline__ void ldsm4_t(uint32_t* r, uint32_t addr) {
    asm volatile("ldmatrix.sync.aligned.m8n8.x4.trans.shared.b16 {%0,%1,%2,%3}, [%4];"
                 : "=r"(r[0]), "=r"(r[1]), "=r"(r[2]), "=r"(r[3]) : "r"(addr));
}
__device__ __forceinline__ void mma_bf16(float* d, const uint32_t* a, uint32_t b0, uint32_t b1) {
    asm volatile(
        "mma.sync.aligned.m16n8k16.row.col.f32.bf16.bf16.f32 "
        "{%0,%1,%2,%3}, {%4,%5,%6,%7}, {%8,%9}, {%0,%1,%2,%3};"
        : "+f"(d[0]), "+f"(d[1]), "+f"(d[2]), "+f"(d[3])
        : "r"(a[0]), "r"(a[1]), "r"(a[2]), "r"(a[3]), "r"(b0), "r"(b1));
}
__device__ __forceinline__ float ex2f(float x) {
    float y;
    asm("ex2.approx.ftz.f32 %0, %1;" : "=f"(y) : "f"(x));
    return y;
}
__device__ __forceinline__ uint32_t cvt2(float a, float b) {
    uint32_t r;
    asm("cvt.rn.bf16x2.f32 %0, %1, %2;" : "=r"(r) : "f"(b), "f"(a));
    return r;
}
__device__ __forceinline__ void split2(float a, float b, uint32_t& hw, uint32_t& lw) {
    hw = cvt2(a, b);
    float ha = __uint_as_float(hw << 16);
    float hb = __uint_as_float(hw & 0xffff0000u);
    lw = cvt2(a - ha, b - hb);
}

// ---------------------------------------------------------------------------
// Prep kernels
// ---------------------------------------------------------------------------
__global__ void prep_w_kernel(const float* __restrict__ Wt, const float* __restrict__ Wp,
                              const float* __restrict__ Wg, const float* __restrict__ Wo) {
    int r = blockIdx.x, c = threadIdx.x;
    if (r < 192) {
        float v = (r < 32) ? Wt[r * CHN + c]
                 : (r < 64) ? Wp[(r - 32) * CHN + c]
                            : Wg[(r - 64) * CHN + c];
        __nv_bfloat16 h = __float2bfloat16(v);
        g_wch[r * CHN + c] = h;
        g_wcl[r * CHN + c] = __float2bfloat16(v - __bfloat162float(h));
    } else if (c < 128) {
        int rr = r - 192;
        float v = Wo[rr * DV + c];
        __nv_bfloat16 h = __float2bfloat16(v);
        g_woh[rr * DV + c] = h;
        g_wol[rr * DV + c] = __float2bfloat16(v - __bfloat162float(h));
    }
}

// x [b][256][4096] -> x^T hi/lo [b][4096][256]
__global__ void transpose_x_kernel(const float* __restrict__ Xg) {
    __shared__ float tile[32][33];
    int b  = blockIdx.z;
    int n0 = blockIdx.x * 32;
    int c0 = blockIdx.y * 32;
    int tx = threadIdx.x & 31, ty = threadIdx.x >> 5;
    const float* xb = Xg + (size_t)b * CHN * SEQ;
#pragma unroll
    for (int i = 0; i < 32; i += 8)
        tile[ty + i][tx] = xb[(size_t)(c0 + ty + i) * SEQ + n0 + tx];
    __syncthreads();
#pragma unroll
    for (int i = 0; i < 32; i += 8) {
        float v = tile[tx][ty + i];
        __nv_bfloat16 h = __float2bfloat16(v);
        size_t off = ((size_t)b * SEQ + n0 + ty + i) * CHN + c0 + tx;
        g_xth[off] = h;
        g_xtl[off] = __float2bfloat16(v - __bfloat162float(h));
    }
}

// ---------------------------------------------------------------------------
// Projection GEMM via mma.sync: C[n][out192] = x^T[n][c] * Wcat[out][c]
// ---------------------------------------------------------------------------
#define PJ_SMEM 110592
__global__ __launch_bounds__(256, 1) void proj_mma_kernel() {
    extern __shared__ char sm[];
    const uint32_t smb = smem_u32(sm);
    const int b    = blockIdx.z;
    const int out0 = blockIdx.y * 64;
    const int n0   = blockIdx.x * 128;
    const int tid  = threadIdx.x;
    const int w    = tid >> 5;
    const int lane = tid & 31;
    const uint32_t lm = lane & 7;
    const uint32_t bk = (lane >> 3) & 1;
    const uint32_t bn = (lane >> 4) & 1;

    auto load_chunk = [&](int buf, int k0) {
        uint32_t base = smb + buf * 55296;
        const char* xh = (const char*)(g_xth + ((size_t)b * SEQ + n0) * CHN + k0);
        const char* xl = (const char*)(g_xtl + ((size_t)b * SEQ + n0) * CHN + k0);
        for (int e = tid; e < 1024; e += 256) {
            int r = e >> 3, s = e & 7;
            cpa16(base + r * 144 + s * 16,         xh + (size_t)r * 512 + s * 16);
            cpa16(base + 18432 + r * 144 + s * 16, xl + (size_t)r * 512 + s * 16);
        }
        const char* wh = (const char*)(g_wch + (size_t)out0 * CHN + k0);
        const char* wl = (const char*)(g_wcl + (size_t)out0 * CHN + k0);
        for (int e = tid; e < 512; e += 256) {
            int r = e >> 3, s = e & 7;
            cpa16(base + 36864 + r * 144 + s * 16, wh + (size_t)r * 512 + s * 16);
            cpa16(base + 46080 + r * 144 + s * 16, wl + (size_t)r * 512 + s * 16);
        }
    };

    float oacc[8][4];
#pragma unroll
    for (int g = 0; g < 8; g++)
#pragma unroll
        for (int k = 0; k < 4; k++) oacc[g][k] = 0.f;

    load_chunk(0, 0);
    CP_COMMIT();

    for (int kb = 0; kb < 4; kb++) {
        int buf = kb & 1;
        if (kb < 3) { load_chunk(buf ^ 1, (kb + 1) * 64); CP_COMMIT(); CP_WAIT1(); }
        else        { CP_WAIT0(); }
        __syncthreads();

        uint32_t ab = smb + buf * 55296;
        uint32_t bb = ab + 36864;
#pragma unroll
        for (int kc = 0; kc < 4; kc++) {
            uint32_t ah4[4], al4[4];
            uint32_t aaddr = ab + (w * 16 + bk * 8 + lm) * 144 + (kc * 16 + bn * 8) * 2;
            ldsm4(ah4, aaddr);
            ldsm4(al4, aaddr + 18432);
#pragma unroll
            for (int jj = 0; jj < 4; jj++) {
                uint32_t baddr = bb + (jj * 16 + bn * 8 + lm) * 144 + (kc * 16 + bk * 8) * 2;
                uint32_t bh4[4], bl4[4];
                ldsm4(bh4, baddr);
                ldsm4(bl4, baddr + 9216);
                mma_bf16(oacc[2 * jj],     ah4, bh4[0], bh4[1]);
                mma_bf16(oacc[2 * jj],     ah4, bl4[0], bl4[1]);
                mma_bf16(oacc[2 * jj],     al4, bh4[0], bh4[1]);
                mma_bf16(oacc[2 * jj + 1], ah4, bh4[2], bh4[3]);
                mma_bf16(oacc[2 * jj + 1], ah4, bl4[2], bl4[3]);
                mma_bf16(oacc[2 * jj + 1], al4, bh4[2], bh4[3]);
            }
        }
        __syncthreads();
    }

    // epilogue
    const int rbase = n0 + w * 16 + (lane >> 2);
    const int qc = (lane & 3) * 2;
#pragma unroll
    for (int g = 0; g < 8; g++) {
        int out = out0 + g * 8 + qc;
#pragma unroll
        for (int rr = 0; rr < 2; rr++) {
            int n = rbase + rr * 8;
            float v0 = oacc[g][rr * 2], v1 = oacc[g][rr * 2 + 1];
            uint32_t hw, lw;
            if (out < 32) {
                split2(v0, v1, hw, lw);
                __nv_bfloat16* base = g_th_t + ((size_t)b * SEQ + n) * 64;
                *(uint32_t*)(base + out) = hw;
                *(uint32_t*)(base + 32 + out) = lw;
            } else if (out < 64) {
                split2(v0 * LOG2E, v1 * LOG2E, hw, lw);
                __nv_bfloat16* base = g_ph_t + ((size_t)b * SEQ + n) * 64;
                *(uint32_t*)(base + (out - 32)) = hw;
                *(uint32_t*)(base + out) = lw;
            } else {
                size_t off = ((size_t)b * SEQ + n) * DV + (out - 64);
                *(uint32_t*)(g_vth + off) = cvt2(v0, v1);   // hi only
            }
        }
    }
}

// ---------------------------------------------------------------------------
// Flash attention (mma.sync; S 3-term bf16, PV (ph+pl)*vh — V hi only).
// Smem: QHI 0..10240 QLO 10240..20480 (80B rows)
//       K buf: 20480 + buf*10240 (hi, +5120 lo)
//       V buf: 40960 + buf*17408  ([64 m][272B] hi only)   total 75776
// ---------------------------------------------------------------------------
#define SM_QHI 0
#define SM_QLO 10240
#define SM_K   20480
#define SM_V   40960
#define FLASH_SMEM 75776

__global__ __launch_bounds__(256, 1) void flash_mma_kernel() {
    extern __shared__ char sm[];
    const uint32_t smb = smem_u32(sm);

    const int b  = blockIdx.y;
    const int q0 = blockIdx.x * QT;
    const int tid  = threadIdx.x;
    const int w    = tid >> 5;
    const int lane = tid & 31;
    const uint32_t lm = lane & 7;
    const uint32_t bk = (lane >> 3) & 1;
    const uint32_t bn = (lane >> 4) & 1;

    // Q tile
    {
        const char* src = (const char*)(g_th_t + ((size_t)b * SEQ + q0) * 64);
        for (int e = tid; e < 1024; e += 256) {
            int r = e >> 3, s = e & 7;
            uint32_t dst = smb + (s < 4 ? (SM_QHI + r * 80 + s * 16)
                                        : (SM_QLO + r * 80 + (s - 4) * 16));
            cpa16(dst, src + r * 128 + s * 16);
        }
    }
    auto load_kv = [&](int buf, int m0) {
        const char* ks = (const char*)(g_ph_t + ((size_t)b * SEQ + m0) * 64);
        uint32_t kb = smb + SM_K + buf * 10240;
        for (int e = tid; e < 512; e += 256) {
            int r = e >> 3, s = e & 7;
            uint32_t dst = kb + (s < 4 ? (r * 80 + s * 16) : (5120 + r * 80 + (s - 4) * 16));
            cpa16(dst, ks + r * 128 + s * 16);
        }
        const char* vh = (const char*)(g_vth + ((size_t)b * SEQ + m0) * DV);
        uint32_t vb = smb + SM_V + buf * 17408;
        for (int e = tid; e < 1024; e += 256) {
            int r = e >> 4, s = e & 15;
            cpa16(vb + r * 272 + s * 16, vh + (size_t)r * 256 + s * 16);
        }
    };
    load_kv(0, 0);
    CP_COMMIT();
    CP_WAIT0();
    __syncthreads();

    uint32_t qh[2][4], ql[2][4];
#pragma unroll
    for (int ks = 0; ks < 2; ks++) {
        uint32_t a = smb + SM_QHI + (w * 16 + bk * 8 + lm) * 80 + (ks * 16 + bn * 8) * 2;
        ldsm4(qh[ks], a);
        ldsm4(ql[ks], a + (SM_QLO - SM_QHI));
    }

    float oacc[16][4];
#pragma unroll
    for (int j = 0; j < 16; j++)
#pragma unroll
        for (int k = 0; k < 4; k++) oacc[j][k] = 0.f;
    float l0 = 0.f, l1 = 0.f;

    for (int t = 0; t < NTILE; t++) {
        const int buf = t & 1;
        if (t + 1 < NTILE) load_kv(buf ^ 1, (t + 1) * MT);
        CP_COMMIT();

        // S = Q K^T (3-term)
        float sacc[8][4];
#pragma unroll
        for (int j = 0; j < 8; j++)
#pragma unroll
            for (int k = 0; k < 4; k++) sacc[j][k] = 0.f;

        const uint32_t kb = smb + SM_K + buf * 10240;
#pragma unroll
        for (int ks = 0; ks < 2; ks++) {
#pragma unroll
            for (int jj = 0; jj < 4; jj++) {
                uint32_t addr = kb + (jj * 16 + bn * 8 + lm) * 80 + (ks * 16 + bk * 8) * 2;
                uint32_t kh[4], kl[4];
                ldsm4(kh, addr);
                ldsm4(kl, addr + 5120);
                mma_bf16(sacc[2 * jj],     qh[ks], kh[0], kh[1]);
                mma_bf16(sacc[2 * jj],     qh[ks], kl[0], kl[1]);
                mma_bf16(sacc[2 * jj],     ql[ks], kh[0], kh[1]);
                mma_bf16(sacc[2 * jj + 1], qh[ks], kh[2], kh[3]);
                mma_bf16(sacc[2 * jj + 1], qh[ks], kl[2], kl[3]);
                mma_bf16(sacc[2 * jj + 1], ql[ks], kh[2], kh[3]);
            }
        }

        // softmax numerators (phi prescaled by log2e); split P hi/lo
        uint32_t ph_[8][2], pl_[8][2];
#pragma unroll
        for (int j = 0; j < 8; j++) {
            float p0 = ex2f(sacc[j][0]);
            float p1 = ex2f(sacc[j][1]);
            float p2 = ex2f(sacc[j][2]);
            float p3 = ex2f(sacc[j][3]);
            l0 += p0 + p1;
            l1 += p2 + p3;
            split2(p0, p1, ph_[j][0], pl_[j][0]);
            split2(p2, p3, ph_[j][1], pl_[j][1]);
        }

        // O += (Phi + Plo) V^T  (V hi only)
        const uint32_t vb = smb + SM_V + buf * 17408;
#pragma unroll
        for (int kk = 0; kk < 4; kk++) {
            uint32_t pah[4] = {ph_[2 * kk][0], ph_[2 * kk][1], ph_[2 * kk + 1][0], ph_[2 * kk + 1][1]};
            uint32_t pal[4] = {pl_[2 * kk][0], pl_[2 * kk][1], pl_[2 * kk + 1][0], pl_[2 * kk + 1][1]};
#pragma unroll
            for (int jj = 0; jj < 8; jj++) {
                uint32_t addr = vb + (kk * 16 + bk * 8 + lm) * 272 + (jj * 16 + bn * 8) * 2;
                uint32_t vh4[4];
                ldsm4_t(vh4, addr);
                mma_bf16(oacc[2 * jj],     pah, vh4[0], vh4[1]);
                mma_bf16(oacc[2 * jj],     pal, vh4[0], vh4[1]);
                mma_bf16(oacc[2 * jj + 1], pah, vh4[2], vh4[3]);
                mma_bf16(oacc[2 * jj + 1], pal, vh4[2], vh4[3]);
            }
        }

        CP_WAIT0();
        __syncthreads();
    }

    // epilogue
    l0 += __shfl_xor_sync(0xffffffffu, l0, 1);
    l0 += __shfl_xor_sync(0xffffffffu, l0, 2);
    l1 += __shfl_xor_sync(0xffffffffu, l1, 1);
    l1 += __shfl_xor_sync(0xffffffffu, l1, 2);
    const float inv0 = 1.f / l0;
    const float inv1 = 1.f / l1;

    const int r0 = q0 + w * 16 + (lane >> 2);
    const int qc = (lane & 3) * 2;
#pragma unroll
    for (int j = 0; j < 16; j++) {
        int c = j * 8 + qc;
        uint32_t hw, lw;
        split2(oacc[j][0] * inv0, oacc[j][1] * inv0, hw, lw);
        size_t off = ((size_t)b * SEQ + r0) * DV + c;
        *(uint32_t*)(g_ath + off) = hw;
        *(uint32_t*)(g_atl + off) = lw;
        split2(oacc[j][2] * inv1, oacc[j][3] * inv1, hw, lw);
        size_t off2 = ((size_t)b * SEQ + r0 + 8) * DV + c;
        *(uint32_t*)(g_ath + off2) = hw;
        *(uint32_t*)(g_atl + off2) = lw;
    }
}

// ---------------------------------------------------------------------------
// Output GEMM via mma.sync
// ---------------------------------------------------------------------------
#define OM_SMEM 104448
__global__ __launch_bounds__(256) void out_mma_kernel(const float* __restrict__ Xg,
                                                      float* __restrict__ Cg,
                                                      const float* __restrict__ gamma_p) {
    extern __shared__ char sm[];
    const uint32_t smb = smem_u32(sm);
    const int b  = blockIdx.z;
    const int n0 = blockIdx.x * 64;
    const int m0 = blockIdx.y * 128;
    const int tid  = threadIdx.x;
    const int w    = tid >> 5;
    const int lane = tid & 31;
    const uint32_t lm = lane & 7;
    const uint32_t bk = (lane >> 3) & 1;
    const uint32_t bn = (lane >> 4) & 1;

    {
        const char* ah = (const char*)(g_woh + (size_t)m0 * DV);
        const char* al = (const char*)(g_wol + (size_t)m0 * DV);
        for (int e = tid; e < 2048; e += 256) {
            int r = e >> 4, s = e & 15;
            cpa16(smb + r * 272 + s * 16,         ah + (size_t)r * 256 + s * 16);
            cpa16(smb + 34816 + r * 272 + s * 16, al + (size_t)r * 256 + s * 16);
        }
        const char* bh = (const char*)(g_ath + ((size_t)b * SEQ + n0) * DV);
        const char* bl = (const char*)(g_atl + ((size_t)b * SEQ + n0) * DV);
        for (int e = tid; e < 1024; e += 256) {
            int r = e >> 4, s = e & 15;
            cpa16(smb + 69632 + r * 272 + s * 16, bh + (size_t)r * 256 + s * 16);
            cpa16(smb + 87040 + r * 272 + s * 16, bl + (size_t)r * 256 + s * 16);
        }
    }
    CP_COMMIT();
    CP_WAIT0();
    __syncthreads();

    float oacc[8][4];
#pragma unroll
    for (int g = 0; g < 8; g++)
#pragma unroll
        for (int k = 0; k < 4; k++) oacc[g][k] = 0.f;

#pragma unroll
    for (int kc = 0; kc < 8; kc++) {
        uint32_t ah4[4], al4[4];
        uint32_t aaddr = smb + (w * 16 + bk * 8 + lm) * 272 + (kc * 16 + bn * 8) * 2;
        ldsm4(ah4, aaddr);
        ldsm4(al4, aaddr + 34816);
#pragma unroll
        for (int jj = 0; jj < 4; jj++) {
            uint32_t baddr = smb + 69632 + (jj * 16 + bn * 8 + lm) * 272 + (kc * 16 + bk * 8) * 2;
            uint32_t bh4[4], bl4[4];
            ldsm4(bh4, baddr);
            ldsm4(bl4, baddr + 17408);
            mma_bf16(oacc[2 * jj],     ah4, bh4[0], bh4[1]);
            mma_bf16(oacc[2 * jj],     ah4, bl4[0], bl4[1]);
            mma_bf16(oacc[2 * jj],     al4, bh4[0], bh4[1]);
            mma_bf16(oacc[2 * jj + 1], ah4, bh4[2], bh4[3]);
            mma_bf16(oacc[2 * jj + 1], ah4, bl4[2], bl4[3]);
            mma_bf16(oacc[2 * jj + 1], al4, bh4[2], bh4[3]);
        }
    }

    const float gm = gamma_p[0];
    const float* xb = Xg + (size_t)b * CHN * SEQ;
    float* cb = Cg + (size_t)b * CHN * SEQ;
    const int r = m0 + w * 16 + (lane >> 2);
    const int qc = (lane & 3) * 2;
#pragma unroll
    for (int g = 0; g < 8; g++) {
        int n = n0 + g * 8 + qc;
#pragma unroll
        for (int rr = 0; rr < 2; rr++) {
            int row = r + rr * 8;
            float2 x2 = *(const float2*)(xb + (size_t)row * SEQ + n);
            float2 o;
            o.x = gm * oacc[g][rr * 2]     + x2.x;
            o.y = gm * oacc[g][rr * 2 + 1] + x2.y;
            *(float2*)(cb + (size_t)row * SEQ + n) = o;
        }
    }
}

// ---------------------------------------------------------------------------
// Launch
// ---------------------------------------------------------------------------
extern "C" void kernel_launch(void* const* d_in, const int* in_sizes, int n_in,
                              void* d_out, int out_size) {
    const float* x     = (const float*)d_in[0];
    const float* Wt    = (const float*)d_in[1];
    const float* Wp    = (const float*)d_in[2];
    const float* Wg    = (const float*)d_in[3];
    const float* Wo    = (const float*)d_in[4];
    const float* gamma = (const float*)d_in[5];
    float* out = (float*)d_out;
    (void)in_sizes; (void)n_in; (void)out_size;

    prep_w_kernel<<<448, 256>>>(Wt, Wp, Wg, Wo);
    transpose_x_kernel<<<dim3(SEQ / 32, CHN / 32, BATCH), 256>>>(x);

    cudaFuncSetAttribute(proj_mma_kernel, cudaFuncAttributeMaxDynamicSharedMemorySize, PJ_SMEM);
    proj_mma_kernel<<<dim3(SEQ / 128, 3, BATCH), 256, PJ_SMEM>>>();

    cudaFuncSetAttribute(flash_mma_kernel, cudaFuncAttributeMaxDynamicSharedMemorySize, FLASH_SMEM);
    flash_mma_kernel<<<dim3(SEQ / QT, BATCH), 256, FLASH_SMEM>>>();

    cudaFuncSetAttribute(out_mma_kernel, cudaFuncAttributeMaxDynamicSharedMemorySize, OM_SMEM);
    out_mma_kernel<<<dim3(SEQ / 64, CHN / 128, BATCH), 256, OM_SMEM>>>(x, out, gamma);
}